// round 1
// baseline (speedup 1.0000x reference)
#include <cuda_runtime.h>
#include <cstdint>
#include <cstddef>

// GemmRS: out[g, n] = sum_s sum_k input[s, g, k] * weight[s, n, k]
//   input  [8, 8192, 512] fp32
//   weight [8, 1024, 512] fp32
//   out    [8192, 1024]   fp32 (flattened [8,1024,1024])
// Single GEMM: M=8192, N=1024, K=4096 (K = s*512 + k, tiles never straddle s).

constexpr int WSIZE = 8;
constexpr int MTOT  = 8192;
constexpr int KLOC  = 512;
constexpr int NTOT  = 1024;
constexpr int KTOT  = WSIZE * KLOC;   // 4096

constexpr int BM = 128;
constexpr int BN = 128;
constexpr int BK = 16;
constexpr int NKT = KTOT / BK;        // 256 k-tiles

__global__ __launch_bounds__(256, 2)
void gemm_rs_kernel(const float* __restrict__ A,   // [WS, MTOT, KLOC]
                    const float* __restrict__ W,   // [WS, NTOT, KLOC]
                    float* __restrict__ C)         // [MTOT, NTOT]
{
    __shared__ float As[2][BK][BM];
    __shared__ float Bs[2][BK][BN];

    const int tid = threadIdx.x;
    const int tx  = tid & 15;         // 0..15 -> N direction
    const int ty  = tid >> 4;         // 0..15 -> M direction
    const int bm  = blockIdx.y * BM;
    const int bn  = blockIdx.x * BN;

    // Loader mapping: 128 threads load rows with k-cols [0,8), 128 with [8,16).
    // Within a warp all lanes share lc and have consecutive lrow -> STS conflict-free.
    const int lrow = tid & 127;
    const int lc   = (tid >> 7) * 8;

    float acc[8][8];
#pragma unroll
    for (int i = 0; i < 8; ++i)
#pragma unroll
        for (int j = 0; j < 8; ++j) acc[i][j] = 0.f;

    // ---- prologue: tile 0 (s = 0, kl = 0) ----
    {
        const float* ap = A + ((size_t)(bm + lrow)) * KLOC + lc;
        const float* bp = W + ((size_t)(bn + lrow)) * KLOC + lc;
        float4 ra0 = *(const float4*)ap;
        float4 ra1 = *(const float4*)(ap + 4);
        float4 rb0 = *(const float4*)bp;
        float4 rb1 = *(const float4*)(bp + 4);
        As[0][lc + 0][lrow] = ra0.x; As[0][lc + 1][lrow] = ra0.y;
        As[0][lc + 2][lrow] = ra0.z; As[0][lc + 3][lrow] = ra0.w;
        As[0][lc + 4][lrow] = ra1.x; As[0][lc + 5][lrow] = ra1.y;
        As[0][lc + 6][lrow] = ra1.z; As[0][lc + 7][lrow] = ra1.w;
        Bs[0][lc + 0][lrow] = rb0.x; Bs[0][lc + 1][lrow] = rb0.y;
        Bs[0][lc + 2][lrow] = rb0.z; Bs[0][lc + 3][lrow] = rb0.w;
        Bs[0][lc + 4][lrow] = rb1.x; Bs[0][lc + 5][lrow] = rb1.y;
        Bs[0][lc + 6][lrow] = rb1.z; Bs[0][lc + 7][lrow] = rb1.w;
    }
    __syncthreads();

#pragma unroll 1
    for (int kt = 0; kt < NKT; ++kt) {
        const int buf = kt & 1;
        const bool has_next = (kt + 1 < NKT);

        // Stage next tile's gmem loads into registers (overlap LDG with FFMAs).
        float4 ra0 = make_float4(0.f, 0.f, 0.f, 0.f), ra1 = ra0, rb0 = ra0, rb1 = ra0;
        if (has_next) {
            const int kg = (kt + 1) * BK;
            const int s  = kg >> 9;               // KLOC = 512
            const int kl = kg & (KLOC - 1);
            const float* ap = A + ((size_t)s * MTOT + bm + lrow) * KLOC + kl + lc;
            const float* bp = W + ((size_t)s * NTOT + bn + lrow) * KLOC + kl + lc;
            ra0 = *(const float4*)ap;
            ra1 = *(const float4*)(ap + 4);
            rb0 = *(const float4*)bp;
            rb1 = *(const float4*)(bp + 4);
        }

        // ---- compute current tile ----
#pragma unroll
        for (int kk = 0; kk < BK; ++kk) {
            // A-reads broadcast across tx (free); B-reads: two 128B-phase-clean groups.
            float4 a0 = *(const float4*)&As[buf][kk][ty * 4];
            float4 a1 = *(const float4*)&As[buf][kk][64 + ty * 4];
            float4 b0 = *(const float4*)&Bs[buf][kk][tx * 4];
            float4 b1 = *(const float4*)&Bs[buf][kk][64 + tx * 4];
            float a[8] = {a0.x, a0.y, a0.z, a0.w, a1.x, a1.y, a1.z, a1.w};
            float b[8] = {b0.x, b0.y, b0.z, b0.w, b1.x, b1.y, b1.z, b1.w};
#pragma unroll
            for (int i = 0; i < 8; ++i)
#pragma unroll
                for (int j = 0; j < 8; ++j)
                    acc[i][j] += a[i] * b[j];
        }

        // ---- commit staged tile to the other buffer ----
        if (has_next) {
            const int nb = buf ^ 1;
            As[nb][lc + 0][lrow] = ra0.x; As[nb][lc + 1][lrow] = ra0.y;
            As[nb][lc + 2][lrow] = ra0.z; As[nb][lc + 3][lrow] = ra0.w;
            As[nb][lc + 4][lrow] = ra1.x; As[nb][lc + 5][lrow] = ra1.y;
            As[nb][lc + 6][lrow] = ra1.z; As[nb][lc + 7][lrow] = ra1.w;
            Bs[nb][lc + 0][lrow] = rb0.x; Bs[nb][lc + 1][lrow] = rb0.y;
            Bs[nb][lc + 2][lrow] = rb0.z; Bs[nb][lc + 3][lrow] = rb0.w;
            Bs[nb][lc + 4][lrow] = rb1.x; Bs[nb][lc + 5][lrow] = rb1.y;
            Bs[nb][lc + 6][lrow] = rb1.z; Bs[nb][lc + 7][lrow] = rb1.w;
        }
        __syncthreads();
    }

    // ---- epilogue: rows are {ty*4+i} and {64+ty*4+i}; cols {tx*4+j} and {64+tx*4+j} ----
#pragma unroll
    for (int i = 0; i < 8; ++i) {
        const int row = bm + (i < 4 ? ty * 4 + i : 64 + ty * 4 + (i - 4));
        float* cp = C + (size_t)row * NTOT + bn;
        float4 v0 = make_float4(acc[i][0], acc[i][1], acc[i][2], acc[i][3]);
        float4 v1 = make_float4(acc[i][4], acc[i][5], acc[i][6], acc[i][7]);
        *(float4*)(cp + tx * 4)      = v0;
        *(float4*)(cp + 64 + tx * 4) = v1;
    }
}

extern "C" void kernel_launch(void* const* d_in, const int* in_sizes, int n_in,
                              void* d_out, int out_size) {
    const float* A = (const float*)d_in[0];   // input  [8, 8192, 512]
    const float* W = (const float*)d_in[1];   // weight [8, 1024, 512]
    float* C = (float*)d_out;                 // out    [8192, 1024]
    (void)in_sizes; (void)n_in; (void)out_size;

    dim3 grid(NTOT / BN, MTOT / BM);          // (8, 64) = 512 CTAs
    gemm_rs_kernel<<<grid, 256>>>(A, W, C);
}

// round 3
// speedup vs baseline: 2.2073x; 2.2073x over previous
#include <cuda_runtime.h>
#include <cuda_bf16.h>
#include <cstdint>
#include <cstddef>

// ---------------------------------------------------------------------------
// GemmRS: out[g,n] = sum_{s,k} A[s,g,k] * W[s,n,k]
//   == one GEMM  M=8192, N=1024, K=4096 (K concatenated over s).
// fp32 -> bf16 hi/lo 3-term split along K (K' = 12288):
//   a*b ~= ha*hb + la*hb + ha*lb   (A pattern [ha,la,ha], B pattern [hb,hb,lb])
// Tensor cores via mma.sync.m16n8k16 (baseline PTX; tcgen05 needs compute_103a
// which this toolchain's PTX target does not enable).
// ---------------------------------------------------------------------------

#define MTOT 8192
#define NTOT 1024
#define KP   12288            // 3 * 4096 bf16
#define BK   64                // bf16 per chunk (128 bytes)
#define NCHUNK (KP / BK)       // 192
#define BMT  128
#define BNT  128
#define STAGE_BYTES 32768      // A 16KB + B 16KB
#define NSTAGE 4

__device__ __nv_bfloat16 g_Aext[(size_t)MTOT * KP];   // [8192, 12288] K-major
__device__ __nv_bfloat16 g_Bext[(size_t)NTOT * KP];   // [1024, 12288] K-major

static __device__ __forceinline__ uint32_t smem_u32(const void* p) {
    uint32_t a;
    asm("{ .reg .u64 t; cvta.to.shared.u64 t, %1; cvt.u32.u64 %0, t; }"
        : "=r"(a) : "l"(p));
    return a;
}
static __device__ __forceinline__ void ldsm_x4(uint32_t& r0, uint32_t& r1,
                                               uint32_t& r2, uint32_t& r3,
                                               uint32_t addr) {
    asm volatile("ldmatrix.sync.aligned.m8n8.x4.shared.b16 {%0,%1,%2,%3}, [%4];"
                 : "=r"(r0), "=r"(r1), "=r"(r2), "=r"(r3) : "r"(addr));
}
static __device__ __forceinline__ void mma16816(float* c, const uint32_t* a,
                                                const uint32_t* b) {
    asm volatile(
        "mma.sync.aligned.m16n8k16.row.col.f32.bf16.bf16.f32 "
        "{%0,%1,%2,%3}, {%4,%5,%6,%7}, {%8,%9}, {%0,%1,%2,%3};"
        : "+f"(c[0]), "+f"(c[1]), "+f"(c[2]), "+f"(c[3])
        : "r"(a[0]), "r"(a[1]), "r"(a[2]), "r"(a[3]), "r"(b[0]), "r"(b[1]));
}

// ----------------------------- prepass kernels -----------------------------
__global__ __launch_bounds__(256) void split_a_kernel(const float* __restrict__ A) {
    const int gid = blockIdx.x * 256 + threadIdx.x;
    const int m   = gid >> 8;
    const int k0  = (gid & 255) << 4;
    const int s   = k0 >> 9;
    const int kl  = k0 & 511;
    const float4* src = (const float4*)(A + ((size_t)s * MTOT + m) * 512 + kl);
    float4 v0 = src[0], v1 = src[1], v2 = src[2], v3 = src[3];
    float x[16] = {v0.x,v0.y,v0.z,v0.w, v1.x,v1.y,v1.z,v1.w,
                   v2.x,v2.y,v2.z,v2.w, v3.x,v3.y,v3.z,v3.w};
    uint32_t w[24];
#pragma unroll
    for (int p = 0; p < 8; ++p) {
        float xa = x[2*p], xb = x[2*p+1];
        __nv_bfloat16 ha = __float2bfloat16(xa);
        __nv_bfloat16 la = __float2bfloat16(xa - __bfloat162float(ha));
        __nv_bfloat16 hb = __float2bfloat16(xb);
        __nv_bfloat16 lb = __float2bfloat16(xb - __bfloat162float(hb));
        uint32_t uha = __bfloat16_as_ushort(ha), ula = __bfloat16_as_ushort(la);
        uint32_t uhb = __bfloat16_as_ushort(hb), ulb = __bfloat16_as_ushort(lb);
        // per element e: [h_e, l_e, h_e]
        w[3*p + 0] = uha | (ula << 16);
        w[3*p + 1] = uha | (uhb << 16);
        w[3*p + 2] = ulb | (uhb << 16);
    }
    uint4* dst = (uint4*)(g_Aext + (size_t)m * KP + 3 * (size_t)k0);
#pragma unroll
    for (int i = 0; i < 6; ++i)
        dst[i] = make_uint4(w[4*i], w[4*i+1], w[4*i+2], w[4*i+3]);
}

__global__ __launch_bounds__(256) void split_b_kernel(const float* __restrict__ W) {
    const int gid = blockIdx.x * 256 + threadIdx.x;
    const int n   = gid >> 8;
    const int k0  = (gid & 255) << 4;
    const int s   = k0 >> 9;
    const int kl  = k0 & 511;
    const float4* src = (const float4*)(W + ((size_t)s * NTOT + n) * 512 + kl);
    float4 v0 = src[0], v1 = src[1], v2 = src[2], v3 = src[3];
    float x[16] = {v0.x,v0.y,v0.z,v0.w, v1.x,v1.y,v1.z,v1.w,
                   v2.x,v2.y,v2.z,v2.w, v3.x,v3.y,v3.z,v3.w};
    uint32_t w[24];
#pragma unroll
    for (int p = 0; p < 8; ++p) {
        float xa = x[2*p], xb = x[2*p+1];
        __nv_bfloat16 ha = __float2bfloat16(xa);
        __nv_bfloat16 la = __float2bfloat16(xa - __bfloat162float(ha));
        __nv_bfloat16 hb = __float2bfloat16(xb);
        __nv_bfloat16 lb = __float2bfloat16(xb - __bfloat162float(hb));
        uint32_t uha = __bfloat16_as_ushort(ha), ula = __bfloat16_as_ushort(la);
        uint32_t uhb = __bfloat16_as_ushort(hb), ulb = __bfloat16_as_ushort(lb);
        // per element e: [h_e, h_e, l_e]
        w[3*p + 0] = uha | (uha << 16);
        w[3*p + 1] = ula | (uhb << 16);
        w[3*p + 2] = uhb | (ulb << 16);
    }
    uint4* dst = (uint4*)(g_Bext + (size_t)n * KP + 3 * (size_t)k0);
#pragma unroll
    for (int i = 0; i < 6; ++i)
        dst[i] = make_uint4(w[4*i], w[4*i+1], w[4*i+2], w[4*i+3]);
}

// ----------------------------- main GEMM ----------------------------------
// CTA 128x128, 8 warps in 4(M)x2(N); warp tile 32(M)x64(N); BK=64.
// SMEM tiles SW128-swizzled; swizzle XOR mask reduces to (row&7)<<4.
__global__ __launch_bounds__(256, 1)
void gemm_mma_bf16x3(float* __restrict__ C) {
    extern __shared__ char dsm[];
    const uint32_t sbase = smem_u32(dsm);

    const int tid  = threadIdx.x;
    const int wid  = tid >> 5;
    const int lane = tid & 31;
    const int wm   = wid & 3;          // M group (x32)
    const int wn   = wid >> 2;         // N group (x64)
    const int bm   = blockIdx.y * BMT;
    const int bn   = blockIdx.x * BNT;

    // ---- cp.async mapping: per thread 4 A chunks + 4 B chunks of 16B ----
    const int rowA = tid >> 3;          // 0..31
    const int cg   = tid & 7;
    uint32_t a_off[4], b_off[4];
#pragma unroll
    for (int i = 0; i < 4; ++i) {
        uint32_t r = rowA + 32 * i;
        uint32_t o = r * 128u + (uint32_t)cg * 16u;
        uint32_t sw = o ^ ((o >> 3) & 0x70u);
        a_off[i] = sw;
        b_off[i] = sw + 16384u;
    }
    const char* pA = (const char*)(g_Aext + (size_t)(bm + rowA) * KP + cg * 8);
    const char* pB = (const char*)(g_Bext + (size_t)(bn + rowA) * KP + cg * 8);

    auto load_chunk = [&](int s) {
        const uint32_t sb = sbase + (uint32_t)s * STAGE_BYTES;
#pragma unroll
        for (int i = 0; i < 4; ++i)
            asm volatile("cp.async.cg.shared.global [%0], [%1], 16;"
                         :: "r"(sb + a_off[i]),
                            "l"(pA + (size_t)i * (32 * KP * 2)) : "memory");
#pragma unroll
        for (int i = 0; i < 4; ++i)
            asm volatile("cp.async.cg.shared.global [%0], [%1], 16;"
                         :: "r"(sb + b_off[i]),
                            "l"(pB + (size_t)i * (32 * KP * 2)) : "memory");
        asm volatile("cp.async.commit_group;" ::: "memory");
        pA += 128;   // 64 bf16 along K'
        pB += 128;
    };

    // ---- ldmatrix per-lane relative offsets (stage-independent) ----
    // A x4 (one m16 tile): lanes 0-15 -> rows m0+lane, k+0; 16-31 -> rows, k+16.
    uint32_t a_rel[2], a_msk[2];
#pragma unroll
    for (int mt = 0; mt < 2; ++mt) {
        uint32_t m = wm * 32 + mt * 16 + (lane & 15);
        a_rel[mt] = m * 128u;
        a_msk[mt] = ((m & 7u) << 4) ^ ((uint32_t)(lane >> 4) * 16u);
    }
    // B x4 (two n8 tiles): lanes (g=lane>>3): n = n0+(g>>1)*8+(lane&7), k+(g&1)*16
    uint32_t b_rel[4], b_msk[4];
#pragma unroll
    for (int np = 0; np < 4; ++np) {
        uint32_t n = wn * 64 + np * 16 + ((uint32_t)((lane >> 4) & 1) * 8u) + (lane & 7);
        b_rel[np] = 16384u + n * 128u;
        b_msk[np] = ((n & 7u) << 4) ^ ((uint32_t)((lane >> 3) & 1) * 16u);
    }

    float acc[2][8][4];
#pragma unroll
    for (int mt = 0; mt < 2; ++mt)
#pragma unroll
        for (int nt = 0; nt < 8; ++nt)
#pragma unroll
            for (int j = 0; j < 4; ++j) acc[mt][nt][j] = 0.f;

    load_chunk(0); load_chunk(1); load_chunk(2);

#pragma unroll 1
    for (int c = 0; c < NCHUNK; ++c) {
        asm volatile("cp.async.wait_group 2;" ::: "memory");
        __syncthreads();
        const uint32_t stg = sbase + (uint32_t)(c & 3) * STAGE_BYTES;

#pragma unroll
        for (int ks = 0; ks < 4; ++ks) {
            const uint32_t kb = (uint32_t)ks * 32u;
            uint32_t a[2][4], b[4][4];
#pragma unroll
            for (int mt = 0; mt < 2; ++mt)
                ldsm_x4(a[mt][0], a[mt][1], a[mt][2], a[mt][3],
                        stg + a_rel[mt] + (kb ^ a_msk[mt]));
#pragma unroll
            for (int np = 0; np < 4; ++np)
                ldsm_x4(b[np][0], b[np][1], b[np][2], b[np][3],
                        stg + b_rel[np] + (kb ^ b_msk[np]));
#pragma unroll
            for (int mt = 0; mt < 2; ++mt)
#pragma unroll
                for (int np = 0; np < 4; ++np) {
                    mma16816(acc[mt][np * 2 + 0], a[mt], &b[np][0]);
                    mma16816(acc[mt][np * 2 + 1], a[mt], &b[np][2]);
                }
        }
        __syncthreads();
        if (c + 3 < NCHUNK) load_chunk((c + 3) & 3);
    }

    // ---- epilogue: direct float2 stores ----
#pragma unroll
    for (int mt = 0; mt < 2; ++mt) {
        const int row0 = bm + wm * 32 + mt * 16 + (lane >> 2);
#pragma unroll
        for (int nt = 0; nt < 8; ++nt) {
            const int col = bn + wn * 64 + nt * 8 + (lane & 3) * 2;
            float* c0 = C + (size_t)row0 * NTOT + col;
            float* c1 = c0 + 8 * NTOT;
            *(float2*)c0 = make_float2(acc[mt][nt][0], acc[mt][nt][1]);
            *(float2*)c1 = make_float2(acc[mt][nt][2], acc[mt][nt][3]);
        }
    }
}

// ----------------------------- launcher -----------------------------------
extern "C" void kernel_launch(void* const* d_in, const int* in_sizes, int n_in,
                              void* d_out, int out_size) {
    const float* A = (const float*)d_in[0];   // [8, 8192, 512]
    const float* W = (const float*)d_in[1];   // [8, 1024, 512]
    float* C = (float*)d_out;                 // [8192, 1024]
    (void)in_sizes; (void)n_in; (void)out_size;

    const int smem_bytes = NSTAGE * STAGE_BYTES;   // 128 KB
    static bool attr_done = false;                 // host-side config only
    if (!attr_done) {
        cudaFuncSetAttribute(gemm_mma_bf16x3,
                             cudaFuncAttributeMaxDynamicSharedMemorySize, smem_bytes);
        attr_done = true;
    }

    split_a_kernel<<<MTOT, 256>>>(A);
    split_b_kernel<<<NTOT, 256>>>(W);

    dim3 grid(NTOT / BNT, MTOT / BMT);   // (8, 64) = 512 CTAs
    gemm_mma_bf16x3<<<grid, 256, smem_bytes>>>(C);
}

// round 4
// speedup vs baseline: 2.8984x; 1.3131x over previous
#include <cuda_runtime.h>
#include <cuda_bf16.h>
#include <cstdint>
#include <cstddef>

// ---------------------------------------------------------------------------
// GemmRS: out[g,n] = sum_{s,k} A[s,g,k] * W[s,n,k]
//   == one GEMM M=8192, N=1024, K=4096.
// fp32 -> bf16 hi/lo split, 3 products in phases along K' (sum order free):
//   phase0: ha.hb (chunks 0..63), phase1: la.hb (64..127), phase2: ha.lb (128..191)
// Physical storage has NO duplication:
//   g_A[m][0:4096]=ha, [4096:8192]=la    (134 MB)
//   g_B[n][0:4096]=hb, [4096:8192]=lb    ( 17 MB)
// Chunk c (64 bf16 = 128B):  A col = (c&127)*64 ;  B col = (c<128 ? c&63 : c-64)*64
// ---------------------------------------------------------------------------

#define MTOT 8192
#define NTOT 1024
#define K2   8192              // 2 * 4096 bf16 per row (hi|lo planes)
#define NCHUNK 192
#define BMT  128
#define BNT  128
#define STAGE_BYTES 32768      // A 16KB + B 16KB
#define NSTAGE 3

__device__ __nv_bfloat16 g_A[(size_t)MTOT * K2];
__device__ __nv_bfloat16 g_B[(size_t)NTOT * K2];

static __device__ __forceinline__ uint32_t smem_u32(const void* p) {
    uint32_t a;
    asm("{ .reg .u64 t; cvta.to.shared.u64 t, %1; cvt.u32.u64 %0, t; }"
        : "=r"(a) : "l"(p));
    return a;
}
static __device__ __forceinline__ void ldsm_x4(uint32_t& r0, uint32_t& r1,
                                               uint32_t& r2, uint32_t& r3,
                                               uint32_t addr) {
    asm volatile("ldmatrix.sync.aligned.m8n8.x4.shared.b16 {%0,%1,%2,%3}, [%4];"
                 : "=r"(r0), "=r"(r1), "=r"(r2), "=r"(r3) : "r"(addr));
}
static __device__ __forceinline__ void mma16816(float* c, const uint32_t* a,
                                                const uint32_t* b) {
    asm volatile(
        "mma.sync.aligned.m16n8k16.row.col.f32.bf16.bf16.f32 "
        "{%0,%1,%2,%3}, {%4,%5,%6,%7}, {%8,%9}, {%0,%1,%2,%3};"
        : "+f"(c[0]), "+f"(c[1]), "+f"(c[2]), "+f"(c[3])
        : "r"(a[0]), "r"(a[1]), "r"(a[2]), "r"(a[3]), "r"(b[0]), "r"(b[1]));
}

// ------------------------- fused split prepass -----------------------------
// Blocks [0,8192): A row m. Blocks [8192,9216): B row n. 256 thr, 16 floats each.
__global__ __launch_bounds__(256) void split_kernel(const float* __restrict__ A,
                                                    const float* __restrict__ W) {
    const int b = blockIdx.x;
    const int t = threadIdx.x;
    const int k0 = t << 4;             // 0..4080
    const int s  = k0 >> 9;
    const int kl = k0 & 511;

    const bool isA = (b < MTOT);
    const int  row = isA ? b : (b - MTOT);
    const float* src = isA ? (A + ((size_t)s * MTOT + row) * 512 + kl)
                           : (W + ((size_t)s * NTOT + row) * 512 + kl);

    float4 v0 = ((const float4*)src)[0];
    float4 v1 = ((const float4*)src)[1];
    float4 v2 = ((const float4*)src)[2];
    float4 v3 = ((const float4*)src)[3];
    float x[16] = {v0.x,v0.y,v0.z,v0.w, v1.x,v1.y,v1.z,v1.w,
                   v2.x,v2.y,v2.z,v2.w, v3.x,v3.y,v3.z,v3.w};

    uint32_t h[8], l[8];
#pragma unroll
    for (int p = 0; p < 8; ++p) {
        float xa = x[2*p], xb = x[2*p+1];
        __nv_bfloat16 ha = __float2bfloat16(xa);
        __nv_bfloat16 la = __float2bfloat16(xa - __bfloat162float(ha));
        __nv_bfloat16 hb = __float2bfloat16(xb);
        __nv_bfloat16 lb = __float2bfloat16(xb - __bfloat162float(hb));
        h[p] = (uint32_t)__bfloat16_as_ushort(ha) |
               ((uint32_t)__bfloat16_as_ushort(hb) << 16);
        l[p] = (uint32_t)__bfloat16_as_ushort(la) |
               ((uint32_t)__bfloat16_as_ushort(lb) << 16);
    }
    __nv_bfloat16* dstrow = (isA ? g_A : g_B) + (size_t)row * K2;
    uint4* dh = (uint4*)(dstrow + k0);
    uint4* dl = (uint4*)(dstrow + 4096 + k0);
    dh[0] = make_uint4(h[0], h[1], h[2], h[3]);
    dh[1] = make_uint4(h[4], h[5], h[6], h[7]);
    dl[0] = make_uint4(l[0], l[1], l[2], l[3]);
    dl[1] = make_uint4(l[4], l[5], l[6], l[7]);
}

// ----------------------------- main GEMM ----------------------------------
// CTA 128x128, 8 warps 4(M)x2(N), warp tile 32x64, BK=64, 3-stage cp.async,
// occupancy 2 (96KB smem/CTA). SW128-swizzled tiles.
__global__ __launch_bounds__(256, 2)
void gemm_mma_bf16x3(float* __restrict__ C) {
    extern __shared__ char dsm[];
    const uint32_t sbase = smem_u32(dsm);

    const int tid  = threadIdx.x;
    const int wid  = tid >> 5;
    const int lane = tid & 31;
    const int wm   = wid & 3;
    const int wn   = wid >> 2;
    const int bm   = blockIdx.y * BMT;
    const int bn   = blockIdx.x * BNT;

    // cp.async mapping: thread -> 4 A rows + 4 B rows, 16B each
    const int rowi = tid >> 3;          // 0..31
    const int cg   = tid & 7;
    uint32_t a_off[4], b_off[4];
#pragma unroll
    for (int i = 0; i < 4; ++i) {
        uint32_t o = (uint32_t)(rowi + 32 * i) * 128u + (uint32_t)cg * 16u;
        uint32_t sw = o ^ ((o >> 3) & 0x70u);
        a_off[i] = sw;
        b_off[i] = sw + 16384u;
    }
    const __nv_bfloat16* rowA = g_A + (size_t)(bm + rowi) * K2 + cg * 8;
    const __nv_bfloat16* rowB = g_B + (size_t)(bn + rowi) * K2 + cg * 8;

    auto load_chunk = [&](int c) {
        const int st = c % NSTAGE;
        const uint32_t sb = sbase + (uint32_t)st * STAGE_BYTES;
        const int acol = (c & 127) * 64;
        const int bcol = (c < 128 ? (c & 63) : (c - 64)) * 64;
        const __nv_bfloat16* pa = rowA + acol;
        const __nv_bfloat16* pb = rowB + bcol;
#pragma unroll
        for (int i = 0; i < 4; ++i)
            asm volatile("cp.async.cg.shared.global [%0], [%1], 16;"
                         :: "r"(sb + a_off[i]),
                            "l"(pa + (size_t)i * (32 * K2)) : "memory");
#pragma unroll
        for (int i = 0; i < 4; ++i)
            asm volatile("cp.async.cg.shared.global [%0], [%1], 16;"
                         :: "r"(sb + b_off[i]),
                            "l"(pb + (size_t)i * (32 * K2)) : "memory");
        asm volatile("cp.async.commit_group;" ::: "memory");
    };

    // ldmatrix per-lane offsets (stage-relative)
    uint32_t a_rel[2], a_msk[2];
#pragma unroll
    for (int mt = 0; mt < 2; ++mt) {
        uint32_t m = wm * 32 + mt * 16 + (lane & 15);
        a_rel[mt] = m * 128u;
        a_msk[mt] = ((m & 7u) << 4) ^ ((uint32_t)(lane >> 4) * 16u);
    }
    uint32_t b_rel[4], b_msk[4];
#pragma unroll
    for (int np = 0; np < 4; ++np) {
        uint32_t n = wn * 64 + np * 16 + ((uint32_t)((lane >> 4) & 1) * 8u) + (lane & 7);
        b_rel[np] = 16384u + n * 128u;
        b_msk[np] = ((n & 7u) << 4) ^ ((uint32_t)((lane >> 3) & 1) * 16u);
    }

    float acc[2][8][4];
#pragma unroll
    for (int mt = 0; mt < 2; ++mt)
#pragma unroll
        for (int nt = 0; nt < 8; ++nt)
#pragma unroll
            for (int j = 0; j < 4; ++j) acc[mt][nt][j] = 0.f;

    load_chunk(0);
    load_chunk(1);

#pragma unroll 1
    for (int c = 0; c < NCHUNK; ++c) {
        if (c + 2 < NCHUNK) asm volatile("cp.async.wait_group 1;" ::: "memory");
        else                asm volatile("cp.async.wait_group 0;" ::: "memory");
        __syncthreads();
        if (c + 2 < NCHUNK) load_chunk(c + 2);   // writes stage (c-1)%3: safe post-sync

        const uint32_t stg = sbase + (uint32_t)(c % NSTAGE) * STAGE_BYTES;
#pragma unroll
        for (int ks = 0; ks < 4; ++ks) {
            const uint32_t kb = (uint32_t)ks * 32u;
            uint32_t a[2][4], bfr[4][4];
#pragma unroll
            for (int mt = 0; mt < 2; ++mt)
                ldsm_x4(a[mt][0], a[mt][1], a[mt][2], a[mt][3],
                        stg + a_rel[mt] + (kb ^ a_msk[mt]));
#pragma unroll
            for (int np = 0; np < 4; ++np)
                ldsm_x4(bfr[np][0], bfr[np][1], bfr[np][2], bfr[np][3],
                        stg + b_rel[np] + (kb ^ b_msk[np]));
#pragma unroll
            for (int mt = 0; mt < 2; ++mt)
#pragma unroll
                for (int np = 0; np < 4; ++np) {
                    mma16816(acc[mt][np * 2 + 0], a[mt], &bfr[np][0]);
                    mma16816(acc[mt][np * 2 + 1], a[mt], &bfr[np][2]);
                }
        }
    }

    // epilogue: direct float2 stores (no smem use -> no sync needed)
#pragma unroll
    for (int mt = 0; mt < 2; ++mt) {
        const int row0 = bm + wm * 32 + mt * 16 + (lane >> 2);
#pragma unroll
        for (int nt = 0; nt < 8; ++nt) {
            const int col = bn + wn * 64 + nt * 8 + (lane & 3) * 2;
            float* c0 = C + (size_t)row0 * NTOT + col;
            float* c1 = c0 + 8 * NTOT;
            *(float2*)c0 = make_float2(acc[mt][nt][0], acc[mt][nt][1]);
            *(float2*)c1 = make_float2(acc[mt][nt][2], acc[mt][nt][3]);
        }
    }
}

// ----------------------------- launcher -----------------------------------
extern "C" void kernel_launch(void* const* d_in, const int* in_sizes, int n_in,
                              void* d_out, int out_size) {
    const float* A = (const float*)d_in[0];   // [8, 8192, 512]
    const float* W = (const float*)d_in[1];   // [8, 1024, 512]
    float* C = (float*)d_out;                 // [8192, 1024]
    (void)in_sizes; (void)n_in; (void)out_size;

    const int smem_bytes = NSTAGE * STAGE_BYTES;   // 96 KB
    static bool attr_done = false;                 // host-side config only
    if (!attr_done) {
        cudaFuncSetAttribute(gemm_mma_bf16x3,
                             cudaFuncAttributeMaxDynamicSharedMemorySize, smem_bytes);
        attr_done = true;
    }

    split_kernel<<<MTOT + NTOT, 256>>>(A, W);      // 9216 blocks

    dim3 grid(NTOT / BNT, MTOT / BMT);             // (8, 64) = 512 CTAs
    gemm_mma_bf16x3<<<grid, 256, smem_bytes>>>(C);
}

// round 5
// speedup vs baseline: 4.2373x; 1.4619x over previous
#include <cuda_runtime.h>
#include <cuda_fp16.h>
#include <cstdint>
#include <cstddef>

// ---------------------------------------------------------------------------
// GemmRS: out[g,n] = sum_{s,k} A[s,g,k] * W[s,n,k]
//   == one GEMM M=8192, N=1024, K=4096.
// fp16 single-sided split:
//   A -> ha (fp16, 1 plane);  W*64 -> hb + lb (fp16, 2 planes); epilogue /64.
//   out = sum ha*(hb+lb) = sum ha*b  -> error ~ 2^-11/sqrt(3) ~ 2.8e-4 rel.
// K' = 8192 (two phases over B planes), tensor work 2/3 of bf16 3-term.
// ---------------------------------------------------------------------------

#define MTOT 8192
#define NTOT 1024
#define KA   4096              // A columns (fp16 ha)
#define KB   8192              // B columns (hb | lb planes)
#define NCHUNK 128             // KB / 64
#define BMT  128
#define BNT  128
#define STAGE_BYTES 32768      // A 16KB + B 16KB
#define NSTAGE 3
#define BSCALE 64.0f
#define BSCALE_INV 0.015625f

__device__ __half g_Ah[(size_t)MTOT * KA];   // 67 MB
__device__ __half g_Bs[(size_t)NTOT * KB];   // 16.8 MB

static __device__ __forceinline__ uint32_t smem_u32(const void* p) {
    uint32_t a;
    asm("{ .reg .u64 t; cvta.to.shared.u64 t, %1; cvt.u32.u64 %0, t; }"
        : "=r"(a) : "l"(p));
    return a;
}
static __device__ __forceinline__ void ldsm_x4(uint32_t& r0, uint32_t& r1,
                                               uint32_t& r2, uint32_t& r3,
                                               uint32_t addr) {
    asm volatile("ldmatrix.sync.aligned.m8n8.x4.shared.b16 {%0,%1,%2,%3}, [%4];"
                 : "=r"(r0), "=r"(r1), "=r"(r2), "=r"(r3) : "r"(addr));
}
static __device__ __forceinline__ void mma16816(float* c, const uint32_t* a,
                                                const uint32_t* b) {
    asm volatile(
        "mma.sync.aligned.m16n8k16.row.col.f32.f16.f16.f32 "
        "{%0,%1,%2,%3}, {%4,%5,%6,%7}, {%8,%9}, {%0,%1,%2,%3};"
        : "+f"(c[0]), "+f"(c[1]), "+f"(c[2]), "+f"(c[3])
        : "r"(a[0]), "r"(a[1]), "r"(a[2]), "r"(a[3]), "r"(b[0]), "r"(b[1]));
}

// ------------------------- fused split prepass -----------------------------
// Blocks [0,8192): A row -> fp16 plane. Blocks [8192,9216): W row -> hb|lb.
__global__ __launch_bounds__(256) void split_kernel(const float* __restrict__ A,
                                                    const float* __restrict__ W) {
    const int b = blockIdx.x;
    const int t = threadIdx.x;
    const int k0 = t << 4;             // 16 floats per thread
    const int s  = k0 >> 9;
    const int kl = k0 & 511;

    if (b < MTOT) {
        const float4* src = (const float4*)(A + ((size_t)s * MTOT + b) * 512 + kl);
        float4 v0 = src[0], v1 = src[1], v2 = src[2], v3 = src[3];
        float x[16] = {v0.x,v0.y,v0.z,v0.w, v1.x,v1.y,v1.z,v1.w,
                       v2.x,v2.y,v2.z,v2.w, v3.x,v3.y,v3.z,v3.w};
        uint32_t h[8];
#pragma unroll
        for (int p = 0; p < 8; ++p) {
            __half h0 = __float2half_rn(x[2*p]);
            __half h1 = __float2half_rn(x[2*p+1]);
            h[p] = (uint32_t)__half_as_ushort(h0) |
                   ((uint32_t)__half_as_ushort(h1) << 16);
        }
        uint4* dst = (uint4*)(g_Ah + (size_t)b * KA + k0);
        dst[0] = make_uint4(h[0], h[1], h[2], h[3]);
        dst[1] = make_uint4(h[4], h[5], h[6], h[7]);
    } else {
        const int n = b - MTOT;
        const float4* src = (const float4*)(W + ((size_t)s * NTOT + n) * 512 + kl);
        float4 v0 = src[0], v1 = src[1], v2 = src[2], v3 = src[3];
        float x[16] = {v0.x,v0.y,v0.z,v0.w, v1.x,v1.y,v1.z,v1.w,
                       v2.x,v2.y,v2.z,v2.w, v3.x,v3.y,v3.z,v3.w};
        uint32_t h[8], l[8];
#pragma unroll
        for (int p = 0; p < 8; ++p) {
            float y0 = x[2*p] * BSCALE, y1 = x[2*p+1] * BSCALE;
            __half h0 = __float2half_rn(y0);
            __half l0 = __float2half_rn(y0 - __half2float(h0));
            __half h1 = __float2half_rn(y1);
            __half l1 = __float2half_rn(y1 - __half2float(h1));
            h[p] = (uint32_t)__half_as_ushort(h0) |
                   ((uint32_t)__half_as_ushort(h1) << 16);
            l[p] = (uint32_t)__half_as_ushort(l0) |
                   ((uint32_t)__half_as_ushort(l1) << 16);
        }
        __half* dstrow = g_Bs + (size_t)n * KB;
        uint4* dh = (uint4*)(dstrow + k0);
        uint4* dl = (uint4*)(dstrow + 4096 + k0);
        dh[0] = make_uint4(h[0], h[1], h[2], h[3]);
        dh[1] = make_uint4(h[4], h[5], h[6], h[7]);
        dl[0] = make_uint4(l[0], l[1], l[2], l[3]);
        dl[1] = make_uint4(l[4], l[5], l[6], l[7]);
    }
}

// ----------------------------- main GEMM ----------------------------------
// CTA 128x128, 8 warps 4(M)x2(N), warp tile 32x64, BK=64, 3-stage cp.async,
// occupancy 2. SW128-swizzled smem tiles.
__global__ __launch_bounds__(256, 2)
void gemm_mma_f16(float* __restrict__ C) {
    extern __shared__ char dsm[];
    const uint32_t sbase = smem_u32(dsm);

    const int tid  = threadIdx.x;
    const int wid  = tid >> 5;
    const int lane = tid & 31;
    const int wm   = wid & 3;
    const int wn   = wid >> 2;
    const int bm   = blockIdx.y * BMT;
    const int bn   = blockIdx.x * BNT;

    // cp.async mapping: thread -> 4 A rows + 4 B rows, 16B each
    const int rowi = tid >> 3;          // 0..31
    const int cg   = tid & 7;
    uint32_t a_off[4], b_off[4];
#pragma unroll
    for (int i = 0; i < 4; ++i) {
        uint32_t o = (uint32_t)(rowi + 32 * i) * 128u + (uint32_t)cg * 16u;
        uint32_t sw = o ^ ((o >> 3) & 0x70u);
        a_off[i] = sw;
        b_off[i] = sw + 16384u;
    }
    const __half* rowA = g_Ah + (size_t)(bm + rowi) * KA + cg * 8;
    const __half* rowB = g_Bs + (size_t)(bn + rowi) * KB + cg * 8;

    auto load_chunk = [&](int c) {
        const int st = c % NSTAGE;
        const uint32_t sb = sbase + (uint32_t)st * STAGE_BYTES;
        const __half* pa = rowA + (c & 63) * 64;   // A plane reused both phases
        const __half* pb = rowB + c * 64;          // B planes linear hb|lb
#pragma unroll
        for (int i = 0; i < 4; ++i)
            asm volatile("cp.async.cg.shared.global [%0], [%1], 16;"
                         :: "r"(sb + a_off[i]),
                            "l"(pa + (size_t)i * (32 * KA)) : "memory");
#pragma unroll
        for (int i = 0; i < 4; ++i)
            asm volatile("cp.async.cg.shared.global [%0], [%1], 16;"
                         :: "r"(sb + b_off[i]),
                            "l"(pb + (size_t)i * (32 * KB)) : "memory");
        asm volatile("cp.async.commit_group;" ::: "memory");
    };

    // ldmatrix per-lane offsets (stage-relative)
    uint32_t a_rel[2], a_msk[2];
#pragma unroll
    for (int mt = 0; mt < 2; ++mt) {
        uint32_t m = wm * 32 + mt * 16 + (lane & 15);
        a_rel[mt] = m * 128u;
        a_msk[mt] = ((m & 7u) << 4) ^ ((uint32_t)(lane >> 4) * 16u);
    }
    uint32_t b_rel[4], b_msk[4];
#pragma unroll
    for (int np = 0; np < 4; ++np) {
        uint32_t n = wn * 64 + np * 16 + ((uint32_t)((lane >> 4) & 1) * 8u) + (lane & 7);
        b_rel[np] = 16384u + n * 128u;
        b_msk[np] = ((n & 7u) << 4) ^ ((uint32_t)((lane >> 3) & 1) * 16u);
    }

    float acc[2][8][4];
#pragma unroll
    for (int mt = 0; mt < 2; ++mt)
#pragma unroll
        for (int nt = 0; nt < 8; ++nt)
#pragma unroll
            for (int j = 0; j < 4; ++j) acc[mt][nt][j] = 0.f;

    load_chunk(0);
    load_chunk(1);

#pragma unroll 1
    for (int c = 0; c < NCHUNK; ++c) {
        if (c + 2 < NCHUNK) asm volatile("cp.async.wait_group 1;" ::: "memory");
        else                asm volatile("cp.async.wait_group 0;" ::: "memory");
        __syncthreads();
        if (c + 2 < NCHUNK) load_chunk(c + 2);   // overwrites stage (c-1)%3: post-sync safe

        const uint32_t stg = sbase + (uint32_t)(c % NSTAGE) * STAGE_BYTES;
#pragma unroll
        for (int ks = 0; ks < 4; ++ks) {
            const uint32_t kb = (uint32_t)ks * 32u;
            uint32_t a[2][4], bfr[4][4];
#pragma unroll
            for (int mt = 0; mt < 2; ++mt)
                ldsm_x4(a[mt][0], a[mt][1], a[mt][2], a[mt][3],
                        stg + a_rel[mt] + (kb ^ a_msk[mt]));
#pragma unroll
            for (int np = 0; np < 4; ++np)
                ldsm_x4(bfr[np][0], bfr[np][1], bfr[np][2], bfr[np][3],
                        stg + b_rel[np] + (kb ^ b_msk[np]));
#pragma unroll
            for (int mt = 0; mt < 2; ++mt)
#pragma unroll
                for (int np = 0; np < 4; ++np) {
                    mma16816(acc[mt][np * 2 + 0], a[mt], &bfr[np][0]);
                    mma16816(acc[mt][np * 2 + 1], a[mt], &bfr[np][2]);
                }
        }
    }

    // epilogue: un-scale (x 1/64) and store
#pragma unroll
    for (int mt = 0; mt < 2; ++mt) {
        const int row0 = bm + wm * 32 + mt * 16 + (lane >> 2);
#pragma unroll
        for (int nt = 0; nt < 8; ++nt) {
            const int col = bn + wn * 64 + nt * 8 + (lane & 3) * 2;
            float* c0 = C + (size_t)row0 * NTOT + col;
            float* c1 = c0 + 8 * NTOT;
            *(float2*)c0 = make_float2(acc[mt][nt][0] * BSCALE_INV,
                                       acc[mt][nt][1] * BSCALE_INV);
            *(float2*)c1 = make_float2(acc[mt][nt][2] * BSCALE_INV,
                                       acc[mt][nt][3] * BSCALE_INV);
        }
    }
}

// ----------------------------- launcher -----------------------------------
extern "C" void kernel_launch(void* const* d_in, const int* in_sizes, int n_in,
                              void* d_out, int out_size) {
    const float* A = (const float*)d_in[0];   // [8, 8192, 512]
    const float* W = (const float*)d_in[1];   // [8, 1024, 512]
    float* C = (float*)d_out;                 // [8192, 1024]
    (void)in_sizes; (void)n_in; (void)out_size;

    const int smem_bytes = NSTAGE * STAGE_BYTES;   // 96 KB
    static bool attr_done = false;                 // host-side config only
    if (!attr_done) {
        cudaFuncSetAttribute(gemm_mma_f16,
                             cudaFuncAttributeMaxDynamicSharedMemorySize, smem_bytes);
        attr_done = true;
    }

    split_kernel<<<MTOT + NTOT, 256>>>(A, W);      // 9216 blocks

    dim3 grid(NTOT / BNT, MTOT / BMT);             // (8, 64) = 512 CTAs
    gemm_mma_f16<<<grid, 256, smem_bytes>>>(C);
}